// round 9
// baseline (speedup 1.0000x reference)
#include <cuda_runtime.h>
#include <cuda_bf16.h>
#include <cstdint>

#define DIM      64
#define KCODES   512
#define TPB      256
#define ROWS_CTA 256
#define CHUNK    64
#define NCHUNKS  (KCODES / CHUNK)
#define RESCUE_THRESH 1e-4f

typedef unsigned int u32;

// ---- device scratch (no allocs allowed) ----
__device__ __align__(16) __nv_bfloat16 g_bh[KCODES * DIM];
__device__ __align__(16) __nv_bfloat16 g_bm[KCODES * DIM];
__device__ __align__(16) __nv_bfloat16 g_bl[KCODES * DIM];
__device__ float g_esqd[KCODES];
__device__ float g_partials[4096];
__device__ int   g_counter = 0;

// ---- smem layout (bytes) ----
#define OFF_XSQ 0
#define OFF_ESQ 1024
#define OFF_RED 3072
#define OFF_AH  4096
#define OFF_AM  (OFF_AH + 32768)
#define OFF_AL  (OFF_AM + 32768)
#define OFF_BH  (OFF_AL + 32768)
#define OFF_BM  (OFF_BH + 8192)
#define OFF_BL  (OFF_BM + 8192)
#define SMEM_TOTAL (OFF_BL + 8192)

#define SW128(o) ((o) ^ (((o) >> 3) & 0x70))

__device__ __forceinline__ u32 smem_to_u32(const void* p) {
    u32 a;
    asm("{ .reg .u64 t; cvta.to.shared.u64 t, %1; cvt.u32.u64 %0, t; }" : "=r"(a) : "l"(p));
    return a;
}

#define LDSM_X4(r0, r1, r2, r3, addr) \
    asm volatile("ldmatrix.sync.aligned.m8n8.x4.shared.b16 {%0,%1,%2,%3}, [%4];" \
                 : "=r"(r0), "=r"(r1), "=r"(r2), "=r"(r3) : "r"(addr))

#define MMA_BF16(d, a0, a1, a2, a3, b0, b1) \
    asm volatile("mma.sync.aligned.m16n8k16.row.col.f32.bf16.bf16.f32 " \
                 "{%0,%1,%2,%3}, {%4,%5,%6,%7}, {%8,%9}, {%0,%1,%2,%3};" \
                 : "+f"((d)[0]), "+f"((d)[1]), "+f"((d)[2]), "+f"((d)[3]) \
                 : "r"(a0), "r"(a1), "r"(a2), "r"(a3), "r"(b0), "r"(b1))

// 3-way bf16 split: v = h + m + l + O(v*2^-27)
__device__ __forceinline__ void split3(float v, __nv_bfloat16& h, __nv_bfloat16& m, __nv_bfloat16& l) {
    h = __float2bfloat16_rn(v);
    float r = v - __bfloat162float(h);
    m = __float2bfloat16_rn(r);
    float r2 = r - __bfloat162float(m);
    l = __float2bfloat16_rn(r2);
}
__device__ __forceinline__ u32 pack2(__nv_bfloat16 a, __nv_bfloat16 b) {
    __nv_bfloat162 p; p.x = a; p.y = b;
    return *reinterpret_cast<u32*>(&p);
}

// ---- prep: codebook -> 3 bf16 splits (code-major) + sequential-rounded e_sq ----
__global__ void vq_prep3(const float* __restrict__ cb, int K) {
    int k = blockIdx.x * blockDim.x + threadIdx.x;
    if (k >= K) return;
    const float4* src = reinterpret_cast<const float4*>(cb + (long)k * DIM);
    u32* dh = reinterpret_cast<u32*>(g_bh) + k * (DIM / 2);
    u32* dm = reinterpret_cast<u32*>(g_bm) + k * (DIM / 2);
    u32* dl = reinterpret_cast<u32*>(g_bl) + k * (DIM / 2);
    float s = 0.f;
#pragma unroll
    for (int i = 0; i < DIM / 4; i++) {
        float4 v = src[i];
        s = __fadd_rn(s, __fmul_rn(v.x, v.x));
        s = __fadd_rn(s, __fmul_rn(v.y, v.y));
        s = __fadd_rn(s, __fmul_rn(v.z, v.z));
        s = __fadd_rn(s, __fmul_rn(v.w, v.w));
        __nv_bfloat16 h0, m0, l0, h1, m1, l1, h2, m2, l2, h3, m3, l3;
        split3(v.x, h0, m0, l0); split3(v.y, h1, m1, l1);
        split3(v.z, h2, m2, l2); split3(v.w, h3, m3, l3);
        dh[2 * i] = pack2(h0, h1); dh[2 * i + 1] = pack2(h2, h3);
        dm[2 * i] = pack2(m0, m1); dm[2 * i + 1] = pack2(m2, m3);
        dl[2 * i] = pack2(l0, l1); dl[2 * i + 1] = pack2(l2, l3);
    }
    g_esqd[k] = s;
}

// Exact R5-replica fp32 rescan of all K codes for one row (near-tie rescue).
// 8 fmaf chains in R5's even/odd chunk pattern + identical tree combine.
__device__ __noinline__ int rescue_row(const float* __restrict__ xr,
                                       const float* __restrict__ cb,
                                       const float* __restrict__ sesq,
                                       float xsq, int K) {
    float xv[DIM];
#pragma unroll
    for (int i = 0; i < DIM / 4; i++) {
        float4 v = reinterpret_cast<const float4*>(xr)[i];
        xv[4 * i] = v.x; xv[4 * i + 1] = v.y; xv[4 * i + 2] = v.z; xv[4 * i + 3] = v.w;
    }
    float best = 3.4e38f;
    int   bidx = 0;
#pragma unroll 1
    for (int k = 0; k < K; k++) {
        const float4* er = reinterpret_cast<const float4*>(cb + (long)k * DIM);
        float s0l = 0.f, s0h = 0.f, s1l = 0.f, s1h = 0.f;
        float s2l = 0.f, s2h = 0.f, s3l = 0.f, s3h = 0.f;
#pragma unroll
        for (int i = 0; i < DIM / 4; i++) {
            float4 e = er[i];
            if (i & 1) {
                s2l = fmaf(xv[4 * i],     e.x, s2l);
                s2h = fmaf(xv[4 * i + 1], e.y, s2h);
                s3l = fmaf(xv[4 * i + 2], e.z, s3l);
                s3h = fmaf(xv[4 * i + 3], e.w, s3h);
            } else {
                s0l = fmaf(xv[4 * i],     e.x, s0l);
                s0h = fmaf(xv[4 * i + 1], e.y, s0h);
                s1l = fmaf(xv[4 * i + 2], e.z, s1l);
                s1h = fmaf(xv[4 * i + 3], e.w, s1h);
            }
        }
        float dot = __fadd_rn(__fadd_rn(__fadd_rn(s0l, s0h), __fadd_rn(s1l, s1h)),
                              __fadd_rn(__fadd_rn(s2l, s2h), __fadd_rn(s3l, s3h)));
        float s = __fsub_rn(__fadd_rn(xsq, sesq[k]), __fmul_rn(2.0f, dot));
        if (s < best) { best = s; bidx = k; }
    }
    return bidx;
}

// ---- main: HMMA 6-pass emulated-fp32 distances + argmin + near-tie rescue ----
__global__ __launch_bounds__(TPB, 1) void vq_hmma(
    const float* __restrict__ x, const float* __restrict__ cb,
    float* __restrict__ out, int N, int nblocks,
    long q_off, long idx_off, long loss_off, float lscale)
{
    extern __shared__ char smem[];
    float* sxsq = reinterpret_cast<float*>(smem + OFF_XSQ);
    float* sesq = reinterpret_cast<float*>(smem + OFF_ESQ);
    float* sred = reinterpret_cast<float*>(smem + OFF_RED);
    u32 sb = smem_to_u32(smem);
    int tid = threadIdx.x, lane = tid & 31, w = tid >> 5;

    for (int i = tid; i < KCODES; i += TPB) sesq[i] = g_esqd[i];

    long row = (long)blockIdx.x * ROWS_CTA + tid;
    bool valid = row < N;

    // Stage this thread's x row (3 splits, SW128) + sequential-rounded xsq.
    {
        const float4* xr = reinterpret_cast<const float4*>(x + (valid ? row : 0) * DIM);
        float xsq = 0.f;
#pragma unroll
        for (int c = 0; c < 8; c++) {                      // 8 dims per 16B smem unit
            float4 v0 = valid ? xr[2 * c]     : make_float4(0.f, 0.f, 0.f, 0.f);
            float4 v1 = valid ? xr[2 * c + 1] : make_float4(0.f, 0.f, 0.f, 0.f);
            xsq = __fadd_rn(xsq, __fmul_rn(v0.x, v0.x));
            xsq = __fadd_rn(xsq, __fmul_rn(v0.y, v0.y));
            xsq = __fadd_rn(xsq, __fmul_rn(v0.z, v0.z));
            xsq = __fadd_rn(xsq, __fmul_rn(v0.w, v0.w));
            xsq = __fadd_rn(xsq, __fmul_rn(v1.x, v1.x));
            xsq = __fadd_rn(xsq, __fmul_rn(v1.y, v1.y));
            xsq = __fadd_rn(xsq, __fmul_rn(v1.z, v1.z));
            xsq = __fadd_rn(xsq, __fmul_rn(v1.w, v1.w));
            float f[8] = {v0.x, v0.y, v0.z, v0.w, v1.x, v1.y, v1.z, v1.w};
            u32 ph[4], pm[4], pl[4];
#pragma unroll
            for (int j = 0; j < 4; j++) {
                __nv_bfloat16 ah, am, al, bh, bm, bl;
                split3(f[2 * j],     ah, am, al);
                split3(f[2 * j + 1], bh, bm, bl);
                ph[j] = pack2(ah, bh); pm[j] = pack2(am, bm); pl[j] = pack2(al, bl);
            }
            u32 sw = SW128((u32)(tid * 128 + c * 16));
            *reinterpret_cast<uint4*>(smem + OFF_AH + sw) = make_uint4(ph[0], ph[1], ph[2], ph[3]);
            *reinterpret_cast<uint4*>(smem + OFF_AM + sw) = make_uint4(pm[0], pm[1], pm[2], pm[3]);
            *reinterpret_cast<uint4*>(smem + OFF_AL + sw) = make_uint4(pl[0], pl[1], pl[2], pl[3]);
        }
        sxsq[tid] = xsq;
    }

    // ldmatrix geometry (per thread).
    int r4 = lane >> 2;
    int arow0 = w * 32 + (lane & 7) + ((lane >> 3) & 1) * 8;        // m-tile 0 row
    u32 aoff0 = (u32)(arow0 * 128 + ((lane >> 4) & 1) * 16);
    u32 amask0 = (aoff0 >> 3) & 0x70;
    u32 aoff1 = (u32)((arow0 + 16) * 128 + ((lane >> 4) & 1) * 16); // m-tile 1
    u32 amask1 = (aoff1 >> 3) & 0x70;
    int n_local = (lane & 7) + ((lane >> 4) & 1) * 8;               // B x4 covers 2 n-tiles
    u32 bbase = (u32)(n_local * 128 + ((lane >> 3) & 1) * 16);
    u32 bmask = (bbase >> 3) & 0x70;

    __syncthreads();
    float xsqv[4];
#pragma unroll
    for (int c = 0; c < 4; c++)
        xsqv[c] = sxsq[w * 32 + (c >> 1) * 16 + (c & 1) * 8 + r4];

    float best[4]  = {3.4e38f, 3.4e38f, 3.4e38f, 3.4e38f};
    float best2[4] = {3.4e38f, 3.4e38f, 3.4e38f, 3.4e38f};   // runner-up value
    int   bidx[4]  = {0, 0, 0, 0};

    const u32 OFFA[3] = {OFF_AH, OFF_AM, OFF_AL};
    const u32 OFFB[3] = {OFF_BH, OFF_BM, OFF_BL};
    const int SA[6] = {0, 0, 1, 0, 2, 1};                          // hh hm mh hl lh mm
    const int SB[6] = {0, 1, 0, 2, 0, 1};

#pragma unroll 1
    for (int ch = 0; ch < NCHUNKS; ch++) {
        __syncthreads();                                           // prev chunk ldmatrix done
        {
            const uint4* s0 = reinterpret_cast<const uint4*>(g_bh) + ch * 512;
            const uint4* s1 = reinterpret_cast<const uint4*>(g_bm) + ch * 512;
            const uint4* s2 = reinterpret_cast<const uint4*>(g_bl) + ch * 512;
#pragma unroll
            for (int u = tid; u < 512; u += TPB) {
                u32 sw = SW128((u32)(u * 16));
                *reinterpret_cast<uint4*>(smem + OFF_BH + sw) = s0[u];
                *reinterpret_cast<uint4*>(smem + OFF_BM + sw) = s1[u];
                *reinterpret_cast<uint4*>(smem + OFF_BL + sw) = s2[u];
            }
        }
        __syncthreads();

        float acc[2][8][4];
#pragma unroll
        for (int mt = 0; mt < 2; mt++)
#pragma unroll
            for (int nt = 0; nt < 8; nt++)
#pragma unroll
                for (int f = 0; f < 4; f++) acc[mt][nt][f] = 0.f;

#pragma unroll
        for (int p = 0; p < 6; p++) {
            u32 Abase = sb + OFFA[SA[p]];
            u32 Bbase = sb + OFFB[SB[p]];
#pragma unroll
            for (int ks = 0; ks < 4; ks++) {
                u32 a0, a1, a2, a3, c0, c1, c2, c3;
                LDSM_X4(a0, a1, a2, a3, Abase + ((aoff0 + ks * 32) ^ amask0));
                LDSM_X4(c0, c1, c2, c3, Abase + ((aoff1 + ks * 32) ^ amask1));
#pragma unroll
                for (int np = 0; np < 4; np++) {
                    u32 b0, b1, b2, b3;
                    LDSM_X4(b0, b1, b2, b3,
                            Bbase + (((u32)(np * 2048) + bbase + ks * 32) ^ bmask));
                    MMA_BF16(acc[0][np * 2],     a0, a1, a2, a3, b0, b1);
                    MMA_BF16(acc[0][np * 2 + 1], a0, a1, a2, a3, b2, b3);
                    MMA_BF16(acc[1][np * 2],     c0, c1, c2, c3, b0, b1);
                    MMA_BF16(acc[1][np * 2 + 1], c0, c1, c2, c3, b2, b3);
                }
            }
        }

        // Scores: s = fl(fl(xsq+esq) - fl(2*dot)); track best + runner-up.
        int cb0 = ch * 64 + (lane & 3) * 2;
#pragma unroll
        for (int nt = 0; nt < 8; nt++) {
            int code0 = cb0 + nt * 8;
            float2 e2 = *reinterpret_cast<const float2*>(sesq + code0);
#pragma unroll
            for (int mt = 0; mt < 2; mt++) {
                float* a = acc[mt][nt];
#pragma unroll
                for (int fz = 0; fz < 4; fz++) {
                    int slot = mt * 2 + (fz >> 1);
                    int code = code0 + (fz & 1);
                    float eq = (fz & 1) ? e2.y : e2.x;
                    float s = __fsub_rn(__fadd_rn(xsqv[slot], eq), __fmul_rn(2.f, a[fz]));
                    if (s < best[slot]) {
                        best2[slot] = best[slot];
                        best[slot] = s; bidx[slot] = code;
                    } else if (s < best2[slot]) {
                        best2[slot] = s;
                    }
                }
            }
        }
    }

    // Reduce (best, idx, second) across the 4 lanes sharing each row.
#pragma unroll
    for (int off = 1; off <= 2; off <<= 1) {
#pragma unroll
        for (int c = 0; c < 4; c++) {
            float ob1 = __shfl_xor_sync(0xffffffffu, best[c],  off);
            int   oi1 = __shfl_xor_sync(0xffffffffu, bidx[c],  off);
            float ob2 = __shfl_xor_sync(0xffffffffu, best2[c], off);
            if (ob1 < best[c]) {
                best2[c] = fminf(best[c], ob2);
                best[c] = ob1; bidx[c] = oi1;
            } else if (ob1 > best[c]) {
                best2[c] = fminf(best2[c], ob1);
            } else {                                   // equal firsts -> gap 0 (forces rescue)
                bidx[c] = min(bidx[c], oi1);
                best2[c] = ob1;
            }
        }
    }

    // Each lane takes one of its group's 4 rows for the epilogue.
    int q = lane & 3;
    long erow = (long)blockIdx.x * ROWS_CTA + w * 32 + (q >> 1) * 16 + (q & 1) * 8 + r4;
    int  eidx = bidx[q];
    float egap = best2[q] - best[q];
    float lsum = 0.f;
    if (erow < N) {
        const float* xrp = x + erow * DIM;
        // Near-tie rescue: redo this row with the exact fp32 scheme (R5 replica).
        if (egap < RESCUE_THRESH)
            eidx = rescue_row(xrp, cb, sesq, sxsq[w * 32 + (q >> 1) * 16 + (q & 1) * 8 + r4], KCODES);

        const float4* xr = reinterpret_cast<const float4*>(xrp);
        const float4* er = reinterpret_cast<const float4*>(cb + (long)eidx * DIM);
        bool qv = (q_off >= 0) && ((q_off & 3) == 0);
#pragma unroll
        for (int i = 0; i < DIM / 4; i++) {
            float4 xv = xr[i], ev = er[i];
            float d0 = __fsub_rn(ev.x, xv.x), d1 = __fsub_rn(ev.y, xv.y);
            float d2 = __fsub_rn(ev.z, xv.z), d3 = __fsub_rn(ev.w, xv.w);
            lsum += d0 * d0 + d1 * d1 + d2 * d2 + d3 * d3;
            if (q_off >= 0) {
                float* dst = out + q_off + erow * DIM + i * 4;
                if (qv) {
                    *reinterpret_cast<float4*>(dst) =
                        make_float4(__fadd_rn(xv.x, d0), __fadd_rn(xv.y, d1),
                                    __fadd_rn(xv.z, d2), __fadd_rn(xv.w, d3));
                } else {                                   // q_off==1: 4B-aligned only
                    dst[0] = __fadd_rn(xv.x, d0); dst[1] = __fadd_rn(xv.y, d1);
                    dst[2] = __fadd_rn(xv.z, d2); dst[3] = __fadd_rn(xv.w, d3);
                }
            }
        }
        if (idx_off >= 0) out[idx_off + erow] = (float)eidx;
    }

    __shared__ int is_last;
    if (loss_off >= 0) {
        sred[tid] = lsum;
        __syncthreads();
#pragma unroll
        for (int o = TPB / 2; o > 0; o >>= 1) {
            if (tid < o) sred[tid] += sred[tid + o];
            __syncthreads();
        }
        if (tid == 0) {
            g_partials[blockIdx.x] = sred[0];
            __threadfence();
            int done = atomicAdd(&g_counter, 1);
            is_last = (done == nblocks - 1);
        }
        __syncthreads();
        if (is_last) {
            float v = 0.f;
            for (int i = tid; i < nblocks; i += TPB) v += g_partials[i];  // fixed order
            sred[tid] = v;
            __syncthreads();
#pragma unroll
            for (int o = TPB / 2; o > 0; o >>= 1) {
                if (tid < o) sred[tid] += sred[tid + o];
                __syncthreads();
            }
            if (tid == 0) { out[loss_off] = sred[0] * lscale; g_counter = 0; }
        }
    }
}

extern "C" void kernel_launch(void* const* d_in, const int* in_sizes, int n_in,
                              void* d_out, int out_size) {
    const float* a = (const float*)d_in[0];
    const float* b = (const float*)d_in[1];
    long s0 = in_sizes[0], s1 = in_sizes[1];
    const float *x, *cb; long xs, cs;
    if (s0 >= s1) { x = a; xs = s0; cb = b; cs = s1; }
    else          { x = b; xs = s1; cb = a; cs = s0; }

    int K = (int)(cs / DIM);
    int N = (int)(xs / DIM);
    long QN = (long)N * DIM;
    long osz = (long)out_size;

    // Output layout (confirmed): [loss(1), quantized_st(QN), indices(N)]
    long loss_off = -1, q_off = -1, idx_off = -1;
    if      (osz == 1 + QN + N) { loss_off = 0; q_off = 1; idx_off = 1 + QN; }
    else if (osz == QN + N)     { q_off = 0; idx_off = QN; }
    else if (osz == QN)         { q_off = 0; }
    else if (osz == N)          { idx_off = 0; }
    else if (osz == 1)          { loss_off = 0; }
    else                        { loss_off = 0; q_off = 1; idx_off = 1 + QN; }

    float* out = (float*)d_out;
    int blocks = (N + ROWS_CTA - 1) / ROWS_CTA;
    float lscale = (float)(1.25 / ((double)N * (double)DIM));

    cudaFuncSetAttribute(vq_hmma, cudaFuncAttributeMaxDynamicSharedMemorySize, SMEM_TOTAL);

    vq_prep3<<<(K + 127) / 128, 128>>>(cb, K);
    vq_hmma<<<blocks, TPB, SMEM_TOTAL>>>(x, cb, out, N, blocks,
                                         q_off, idx_off, loss_off, lscale);
}

// round 11
// speedup vs baseline: 2.7150x; 2.7150x over previous
#include <cuda_runtime.h>
#include <cuda_bf16.h>
#include <cstdint>

#define DIM      64
#define KCODES   512
#define TPB      256
#define ROWS_CTA 256
#define NCHUNKS  8
#define RESCUE_T 7.6e-5f

typedef unsigned int u32;

// ---- device scratch (no allocs allowed) ----
__device__ __align__(16) __nv_bfloat16 g_bh[KCODES * DIM];
__device__ __align__(16) __nv_bfloat16 g_bm[KCODES * DIM];
__device__ float g_esqd[KCODES];
__device__ float g_partials[4096];
__device__ int   g_counter = 0;

// ---- smem layout (bytes): total 84KB -> 2 CTAs/SM ----
#define OFF_XSQ 0
#define OFF_ESQ 1024
#define OFF_RED 3072
#define OFF_AH  4096
#define OFF_AM  (OFF_AH + 32768)
#define OFF_BH  (OFF_AM + 32768)
#define OFF_BM  (OFF_BH + 8192)
#define SMEM_TOTAL (OFF_BM + 8192)

#define SW128(o) ((o) ^ (((o) >> 3) & 0x70))

__device__ __forceinline__ u32 smem_to_u32(const void* p) {
    u32 a;
    asm("{ .reg .u64 t; cvta.to.shared.u64 t, %1; cvt.u32.u64 %0, t; }" : "=r"(a) : "l"(p));
    return a;
}

#define LDSM_X4(r0, r1, r2, r3, addr) \
    asm volatile("ldmatrix.sync.aligned.m8n8.x4.shared.b16 {%0,%1,%2,%3}, [%4];" \
                 : "=r"(r0), "=r"(r1), "=r"(r2), "=r"(r3) : "r"(addr))

#define MMA_BF16(d, a0, a1, a2, a3, b0, b1) \
    asm volatile("mma.sync.aligned.m16n8k16.row.col.f32.bf16.bf16.f32 " \
                 "{%0,%1,%2,%3}, {%4,%5,%6,%7}, {%8,%9}, {%0,%1,%2,%3};" \
                 : "+f"((d)[0]), "+f"((d)[1]), "+f"((d)[2]), "+f"((d)[3]) \
                 : "r"(a0), "r"(a1), "r"(a2), "r"(a3), "r"(b0), "r"(b1))

// 2-way bf16 split: v = h + m + O(v*2^-18) (residual covered by rescue pass)
__device__ __forceinline__ void split2(float v, __nv_bfloat16& h, __nv_bfloat16& m) {
    h = __float2bfloat16_rn(v);
    m = __float2bfloat16_rn(v - __bfloat162float(h));
}
__device__ __forceinline__ u32 pack2(__nv_bfloat16 a, __nv_bfloat16 b) {
    __nv_bfloat162 p; p.x = a; p.y = b;
    return *reinterpret_cast<u32*>(&p);
}

// ---- prep: codebook -> 2 bf16 splits + sequential-rounded e_sq ----
__global__ void vq_prep2(const float* __restrict__ cb, int K) {
    int k = blockIdx.x * blockDim.x + threadIdx.x;
    if (k >= K) return;
    const float4* src = reinterpret_cast<const float4*>(cb + (long)k * DIM);
    u32* dh = reinterpret_cast<u32*>(g_bh) + k * (DIM / 2);
    u32* dm = reinterpret_cast<u32*>(g_bm) + k * (DIM / 2);
    float s = 0.f;
#pragma unroll
    for (int i = 0; i < DIM / 4; i++) {
        float4 v = src[i];
        s = __fadd_rn(s, __fmul_rn(v.x, v.x));
        s = __fadd_rn(s, __fmul_rn(v.y, v.y));
        s = __fadd_rn(s, __fmul_rn(v.z, v.z));
        s = __fadd_rn(s, __fmul_rn(v.w, v.w));
        __nv_bfloat16 h0, m0, h1, m1, h2, m2, h3, m3;
        split2(v.x, h0, m0); split2(v.y, h1, m1);
        split2(v.z, h2, m2); split2(v.w, h3, m3);
        dh[2 * i] = pack2(h0, h1); dh[2 * i + 1] = pack2(h2, h3);
        dm[2 * i] = pack2(m0, m1); dm[2 * i + 1] = pack2(m2, m3);
    }
    g_esqd[k] = s;
}

// ---- main: HMMA 3-pass distances + argmin + warp-cooperative near-tie rescue ----
__global__ __launch_bounds__(TPB, 2) void vq_hmma(
    const float* __restrict__ x, const float* __restrict__ cb,
    float* __restrict__ out, int N, int nblocks,
    long q_off, long idx_off, long loss_off, float lscale)
{
    extern __shared__ char smem[];
    float* sxsq = reinterpret_cast<float*>(smem + OFF_XSQ);
    float* sesq = reinterpret_cast<float*>(smem + OFF_ESQ);
    float* sred = reinterpret_cast<float*>(smem + OFF_RED);
    u32 sb = smem_to_u32(smem);
    int tid = threadIdx.x, lane = tid & 31, w = tid >> 5;
    long blockbase = (long)blockIdx.x * ROWS_CTA;

    for (int i = tid; i < KCODES; i += TPB) sesq[i] = g_esqd[i];

    long row = blockbase + tid;
    bool valid = row < N;

    // Stage this thread's x row (2 splits, SW128) + sequential-rounded xsq.
    {
        const float4* xr = reinterpret_cast<const float4*>(x + (valid ? row : 0) * DIM);
        float xsq = 0.f;
#pragma unroll
        for (int c = 0; c < 8; c++) {                      // 8 dims per 16B smem unit
            float4 v0 = valid ? xr[2 * c]     : make_float4(0.f, 0.f, 0.f, 0.f);
            float4 v1 = valid ? xr[2 * c + 1] : make_float4(0.f, 0.f, 0.f, 0.f);
            xsq = __fadd_rn(xsq, __fmul_rn(v0.x, v0.x));
            xsq = __fadd_rn(xsq, __fmul_rn(v0.y, v0.y));
            xsq = __fadd_rn(xsq, __fmul_rn(v0.z, v0.z));
            xsq = __fadd_rn(xsq, __fmul_rn(v0.w, v0.w));
            xsq = __fadd_rn(xsq, __fmul_rn(v1.x, v1.x));
            xsq = __fadd_rn(xsq, __fmul_rn(v1.y, v1.y));
            xsq = __fadd_rn(xsq, __fmul_rn(v1.z, v1.z));
            xsq = __fadd_rn(xsq, __fmul_rn(v1.w, v1.w));
            float f[8] = {v0.x, v0.y, v0.z, v0.w, v1.x, v1.y, v1.z, v1.w};
            u32 ph[4], pm[4];
#pragma unroll
            for (int j = 0; j < 4; j++) {
                __nv_bfloat16 ah, am, bh, bm;
                split2(f[2 * j], ah, am);
                split2(f[2 * j + 1], bh, bm);
                ph[j] = pack2(ah, bh); pm[j] = pack2(am, bm);
            }
            u32 sw = SW128((u32)(tid * 128 + c * 16));
            *reinterpret_cast<uint4*>(smem + OFF_AH + sw) = make_uint4(ph[0], ph[1], ph[2], ph[3]);
            *reinterpret_cast<uint4*>(smem + OFF_AM + sw) = make_uint4(pm[0], pm[1], pm[2], pm[3]);
        }
        sxsq[tid] = xsq;
    }

    // ldmatrix geometry (per thread).
    int r4 = lane >> 2;
    int arow0 = w * 32 + (lane & 7) + ((lane >> 3) & 1) * 8;        // m-tile 0 row
    u32 aoff0 = (u32)(arow0 * 128 + ((lane >> 4) & 1) * 16);
    u32 amask0 = (aoff0 >> 3) & 0x70;
    u32 aoff1 = (u32)((arow0 + 16) * 128 + ((lane >> 4) & 1) * 16); // m-tile 1
    u32 amask1 = (aoff1 >> 3) & 0x70;
    int n_local = (lane & 7) + ((lane >> 4) & 1) * 8;               // B x4 covers 2 n-tiles
    u32 bbase = (u32)(n_local * 128 + ((lane >> 3) & 1) * 16);
    u32 bmask = (bbase >> 3) & 0x70;

    __syncthreads();
    float xsqv[4];
#pragma unroll
    for (int c = 0; c < 4; c++)
        xsqv[c] = sxsq[w * 32 + (c >> 1) * 16 + (c & 1) * 8 + r4];

    float best[4]  = {3.4e38f, 3.4e38f, 3.4e38f, 3.4e38f};
    float best2[4] = {3.4e38f, 3.4e38f, 3.4e38f, 3.4e38f};
    int   bidx[4]  = {0, 0, 0, 0};

    const u32 OFFA[3] = {OFF_AH, OFF_AH, OFF_AM};                   // passes: hh, hm, mh
    const u32 OFFB[3] = {OFF_BH, OFF_BM, OFF_BH};

#pragma unroll 1
    for (int ch = 0; ch < NCHUNKS; ch++) {
        __syncthreads();                                            // prev chunk ldmatrix done
        {
            const uint4* s0 = reinterpret_cast<const uint4*>(g_bh) + ch * 512;
            const uint4* s1 = reinterpret_cast<const uint4*>(g_bm) + ch * 512;
#pragma unroll
            for (int u = tid; u < 512; u += TPB) {
                u32 sw = SW128((u32)(u * 16));
                *reinterpret_cast<uint4*>(smem + OFF_BH + sw) = s0[u];
                *reinterpret_cast<uint4*>(smem + OFF_BM + sw) = s1[u];
            }
        }
        __syncthreads();

        float acc[2][8][4];
#pragma unroll
        for (int mt = 0; mt < 2; mt++)
#pragma unroll
            for (int nt = 0; nt < 8; nt++)
#pragma unroll
                for (int f = 0; f < 4; f++) acc[mt][nt][f] = 0.f;

#pragma unroll
        for (int p = 0; p < 3; p++) {
            u32 Abase = sb + OFFA[p];
            u32 Bbase = sb + OFFB[p];
#pragma unroll
            for (int ks = 0; ks < 4; ks++) {
                u32 a0, a1, a2, a3, c0, c1, c2, c3;
                LDSM_X4(a0, a1, a2, a3, Abase + ((aoff0 + ks * 32) ^ amask0));
                LDSM_X4(c0, c1, c2, c3, Abase + ((aoff1 + ks * 32) ^ amask1));
#pragma unroll
                for (int np = 0; np < 4; np++) {
                    u32 b0, b1, b2, b3;
                    LDSM_X4(b0, b1, b2, b3,
                            Bbase + (((u32)(np * 2048) + bbase + ks * 32) ^ bmask));
                    MMA_BF16(acc[0][np * 2],     a0, a1, a2, a3, b0, b1);
                    MMA_BF16(acc[0][np * 2 + 1], a0, a1, a2, a3, b2, b3);
                    MMA_BF16(acc[1][np * 2],     c0, c1, c2, c3, b0, b1);
                    MMA_BF16(acc[1][np * 2 + 1], c0, c1, c2, c3, b2, b3);
                }
            }
        }

        // Scores: s = fl(fl(xsq+esq) - fl(2*dot)); track best + runner-up.
        int cb0 = ch * 64 + (lane & 3) * 2;
#pragma unroll
        for (int nt = 0; nt < 8; nt++) {
            int code0 = cb0 + nt * 8;
            float2 e2 = *reinterpret_cast<const float2*>(sesq + code0);
#pragma unroll
            for (int mt = 0; mt < 2; mt++) {
                float* a = acc[mt][nt];
#pragma unroll
                for (int fz = 0; fz < 4; fz++) {
                    int slot = mt * 2 + (fz >> 1);
                    int code = code0 + (fz & 1);
                    float eq = (fz & 1) ? e2.y : e2.x;
                    float s = __fsub_rn(__fadd_rn(xsqv[slot], eq), __fmul_rn(2.f, a[fz]));
                    if (s < best[slot]) {
                        best2[slot] = best[slot];
                        best[slot] = s; bidx[slot] = code;
                    } else if (s < best2[slot]) {
                        best2[slot] = s;
                    }
                }
            }
        }
    }

    // Reduce (best, idx, second) across the 4 lanes sharing each row.
#pragma unroll
    for (int off = 1; off <= 2; off <<= 1) {
#pragma unroll
        for (int c = 0; c < 4; c++) {
            float ob1 = __shfl_xor_sync(0xffffffffu, best[c],  off);
            int   oi1 = __shfl_xor_sync(0xffffffffu, bidx[c],  off);
            float ob2 = __shfl_xor_sync(0xffffffffu, best2[c], off);
            if (ob1 < best[c]) {
                best2[c] = fminf(best[c], ob2);
                best[c] = ob1; bidx[c] = oi1;
            } else if (ob1 > best[c]) {
                best2[c] = fminf(best2[c], ob1);
            } else {                                   // equal firsts -> gap 0 (forces rescue)
                bidx[c] = min(bidx[c], oi1);
                best2[c] = ob1;
            }
        }
    }

    // Each lane owns one of its group's 4 rows for the epilogue.
    int q = lane & 3;
    int  lrow = w * 32 + (q >> 1) * 16 + (q & 1) * 8 + r4;    // local row in CTA
    long erow = blockbase + lrow;
    int  eidx = bidx[q];
    float egap = best2[q] - best[q];

    // Warp-cooperative near-tie rescue: full K fp32 rescan (R5-exact scheme).
    unsigned need = __ballot_sync(0xffffffffu, (erow < N) && (egap < RESCUE_T));
    while (need) {
        int src = __ffs(need) - 1; need &= need - 1;
        int srow = __shfl_sync(0xffffffffu, lrow, src);
        float rxsq = sxsq[srow];
        const float4* xr = reinterpret_cast<const float4*>(x + (blockbase + srow) * DIM);
        float xv[DIM];
#pragma unroll
        for (int i = 0; i < DIM / 4; i++) {
            float4 v = xr[i];
            xv[4 * i] = v.x; xv[4 * i + 1] = v.y; xv[4 * i + 2] = v.z; xv[4 * i + 3] = v.w;
        }
        float rb = 3.4e38f; int ri = 0;
#pragma unroll 1
        for (int j = 0; j < KCODES / 32; j++) {
            int k = j * 32 + lane;                        // coalesced across lanes
            const float4* er = reinterpret_cast<const float4*>(cb + (long)k * DIM);
            float s0l = 0.f, s0h = 0.f, s1l = 0.f, s1h = 0.f;
            float s2l = 0.f, s2h = 0.f, s3l = 0.f, s3h = 0.f;
#pragma unroll
            for (int i = 0; i < DIM / 4; i++) {
                float4 e = er[i];
                if (i & 1) {
                    s2l = fmaf(xv[4 * i],     e.x, s2l);
                    s2h = fmaf(xv[4 * i + 1], e.y, s2h);
                    s3l = fmaf(xv[4 * i + 2], e.z, s3l);
                    s3h = fmaf(xv[4 * i + 3], e.w, s3h);
                } else {
                    s0l = fmaf(xv[4 * i],     e.x, s0l);
                    s0h = fmaf(xv[4 * i + 1], e.y, s0h);
                    s1l = fmaf(xv[4 * i + 2], e.z, s1l);
                    s1h = fmaf(xv[4 * i + 3], e.w, s1h);
                }
            }
            float dot = __fadd_rn(__fadd_rn(__fadd_rn(s0l, s0h), __fadd_rn(s1l, s1h)),
                                  __fadd_rn(__fadd_rn(s2l, s2h), __fadd_rn(s3l, s3h)));
            float s = __fsub_rn(__fadd_rn(rxsq, sesq[k]), __fmul_rn(2.0f, dot));
            if (s < rb) { rb = s; ri = k; }
        }
#pragma unroll
        for (int off = 16; off > 0; off >>= 1) {           // tie -> smallest index
            float ob = __shfl_xor_sync(0xffffffffu, rb, off);
            int   oi = __shfl_xor_sync(0xffffffffu, ri, off);
            if (ob < rb || (ob == rb && oi < ri)) { rb = ob; ri = oi; }
        }
        if (lane == src) eidx = ri;
    }

    // Epilogue: quantized_st = fl(x + fl(e - x)); per-row loss term.
    float lsum = 0.f;
    if (erow < N) {
        const float4* xr = reinterpret_cast<const float4*>(x + erow * DIM);
        const float4* er = reinterpret_cast<const float4*>(cb + (long)eidx * DIM);
        bool qv = (q_off >= 0) && ((q_off & 3) == 0);
#pragma unroll
        for (int i = 0; i < DIM / 4; i++) {
            float4 xv = xr[i], ev = er[i];
            float d0 = __fsub_rn(ev.x, xv.x), d1 = __fsub_rn(ev.y, xv.y);
            float d2 = __fsub_rn(ev.z, xv.z), d3 = __fsub_rn(ev.w, xv.w);
            lsum += d0 * d0 + d1 * d1 + d2 * d2 + d3 * d3;
            if (q_off >= 0) {
                float* dst = out + q_off + erow * DIM + i * 4;
                if (qv) {
                    *reinterpret_cast<float4*>(dst) =
                        make_float4(__fadd_rn(xv.x, d0), __fadd_rn(xv.y, d1),
                                    __fadd_rn(xv.z, d2), __fadd_rn(xv.w, d3));
                } else {                                   // q_off==1: 4B-aligned only
                    dst[0] = __fadd_rn(xv.x, d0); dst[1] = __fadd_rn(xv.y, d1);
                    dst[2] = __fadd_rn(xv.z, d2); dst[3] = __fadd_rn(xv.w, d3);
                }
            }
        }
        if (idx_off >= 0) out[idx_off + erow] = (float)eidx;
    }

    __shared__ int is_last;
    if (loss_off >= 0) {
        sred[tid] = lsum;
        __syncthreads();
#pragma unroll
        for (int o = TPB / 2; o > 0; o >>= 1) {
            if (tid < o) sred[tid] += sred[tid + o];
            __syncthreads();
        }
        if (tid == 0) {
            g_partials[blockIdx.x] = sred[0];
            __threadfence();
            int done = atomicAdd(&g_counter, 1);
            is_last = (done == nblocks - 1);
        }
        __syncthreads();
        if (is_last) {
            float v = 0.f;
            for (int i = tid; i < nblocks; i += TPB) v += g_partials[i];  // fixed order
            sred[tid] = v;
            __syncthreads();
#pragma unroll
            for (int o = TPB / 2; o > 0; o >>= 1) {
                if (tid < o) sred[tid] += sred[tid + o];
                __syncthreads();
            }
            if (tid == 0) { out[loss_off] = sred[0] * lscale; g_counter = 0; }
        }
    }
}

extern "C" void kernel_launch(void* const* d_in, const int* in_sizes, int n_in,
                              void* d_out, int out_size) {
    const float* a = (const float*)d_in[0];
    const float* b = (const float*)d_in[1];
    long s0 = in_sizes[0], s1 = in_sizes[1];
    const float *x, *cb; long xs, cs;
    if (s0 >= s1) { x = a; xs = s0; cb = b; cs = s1; }
    else          { x = b; xs = s1; cb = a; cs = s0; }

    int K = (int)(cs / DIM);
    int N = (int)(xs / DIM);
    long QN = (long)N * DIM;
    long osz = (long)out_size;

    // Output layout (confirmed): [loss(1), quantized_st(QN), indices(N)]
    long loss_off = -1, q_off = -1, idx_off = -1;
    if      (osz == 1 + QN + N) { loss_off = 0; q_off = 1; idx_off = 1 + QN; }
    else if (osz == QN + N)     { q_off = 0; idx_off = QN; }
    else if (osz == QN)         { q_off = 0; }
    else if (osz == N)          { idx_off = 0; }
    else if (osz == 1)          { loss_off = 0; }
    else                        { loss_off = 0; q_off = 1; idx_off = 1 + QN; }

    float* out = (float*)d_out;
    int blocks = (N + ROWS_CTA - 1) / ROWS_CTA;
    float lscale = (float)(1.25 / ((double)N * (double)DIM));

    cudaFuncSetAttribute(vq_hmma, cudaFuncAttributeMaxDynamicSharedMemorySize, SMEM_TOTAL);

    vq_prep2<<<(K + 127) / 128, 128>>>(cb, K);
    vq_hmma<<<blocks, TPB, SMEM_TOTAL>>>(x, cb, out, N, blocks,
                                         q_off, idx_off, loss_off, lscale);
}

// round 13
// speedup vs baseline: 3.0586x; 1.1265x over previous
#include <cuda_runtime.h>
#include <cuda_bf16.h>
#include <cstdint>

#define DIM      64
#define KCODES   512
#define TPB      512
#define ROWS_CTA 256
#define NCHUNKS  8
#define RESCUE_T 7.6e-5f

typedef unsigned int u32;

// ---- device scratch (no allocs allowed) ----
__device__ __align__(16) __nv_bfloat16 g_bh[KCODES * DIM];
__device__ __align__(16) __nv_bfloat16 g_bm[KCODES * DIM];
__device__ float g_esqd[KCODES];
__device__ float g_partials[4096];
__device__ int   g_counter = 0;

// ---- smem layout (bytes), ~198KB -> 1 CTA/SM; tiles 1024-aligned ----
#define OFF_XSQ 0
#define OFF_ESQ 1024
#define OFF_RED 3072
#define OFF_AH  6144
#define OFF_AM  (OFF_AH + 32768)
#define OFF_BH  (OFF_AM + 32768)
#define OFF_BM  (OFF_BH + 65536)
#define SMEM_TOTAL (OFF_BM + 65536)

#define SW128(o) ((o) ^ (((o) >> 3) & 0x70))

__device__ __forceinline__ u32 smem_to_u32(const void* p) {
    u32 a;
    asm("{ .reg .u64 t; cvta.to.shared.u64 t, %1; cvt.u32.u64 %0, t; }" : "=r"(a) : "l"(p));
    return a;
}

#define LDSM_X4(r0, r1, r2, r3, addr) \
    asm volatile("ldmatrix.sync.aligned.m8n8.x4.shared.b16 {%0,%1,%2,%3}, [%4];" \
                 : "=r"(r0), "=r"(r1), "=r"(r2), "=r"(r3) : "r"(addr))

#define MMA_BF16(d, a0, a1, a2, a3, b0, b1) \
    asm volatile("mma.sync.aligned.m16n8k16.row.col.f32.bf16.bf16.f32 " \
                 "{%0,%1,%2,%3}, {%4,%5,%6,%7}, {%8,%9}, {%0,%1,%2,%3};" \
                 : "+f"((d)[0]), "+f"((d)[1]), "+f"((d)[2]), "+f"((d)[3]) \
                 : "r"(a0), "r"(a1), "r"(a2), "r"(a3), "r"(b0), "r"(b1))

// 2-way bf16 split: v = h + m + O(v*2^-18) (residual covered by rescue pass)
__device__ __forceinline__ void split2(float v, __nv_bfloat16& h, __nv_bfloat16& m) {
    h = __float2bfloat16_rn(v);
    m = __float2bfloat16_rn(v - __bfloat162float(h));
}
__device__ __forceinline__ u32 pack2(__nv_bfloat16 a, __nv_bfloat16 b) {
    __nv_bfloat162 p; p.x = a; p.y = b;
    return *reinterpret_cast<u32*>(&p);
}

// ---- prep: codebook -> 2 bf16 splits + sequential-rounded e_sq ----
__global__ void vq_prep2(const float* __restrict__ cb, int K) {
    int k = blockIdx.x * blockDim.x + threadIdx.x;
    if (k >= K) return;
    const float4* src = reinterpret_cast<const float4*>(cb + (long)k * DIM);
    u32* dh = reinterpret_cast<u32*>(g_bh) + k * (DIM / 2);
    u32* dm = reinterpret_cast<u32*>(g_bm) + k * (DIM / 2);
    float s = 0.f;
#pragma unroll
    for (int i = 0; i < DIM / 4; i++) {
        float4 v = src[i];
        s = __fadd_rn(s, __fmul_rn(v.x, v.x));
        s = __fadd_rn(s, __fmul_rn(v.y, v.y));
        s = __fadd_rn(s, __fmul_rn(v.z, v.z));
        s = __fadd_rn(s, __fmul_rn(v.w, v.w));
        __nv_bfloat16 h0, m0, h1, m1, h2, m2, h3, m3;
        split2(v.x, h0, m0); split2(v.y, h1, m1);
        split2(v.z, h2, m2); split2(v.w, h3, m3);
        dh[2 * i] = pack2(h0, h1); dh[2 * i + 1] = pack2(h2, h3);
        dm[2 * i] = pack2(m0, m1); dm[2 * i + 1] = pack2(m2, m3);
    }
    g_esqd[k] = s;
}

// ---- main: fully-resident B, sync-free HMMA mainloop, hoisted A frags ----
__global__ __launch_bounds__(TPB, 1) void vq_hmma(
    const float* __restrict__ x, const float* __restrict__ cb,
    float* __restrict__ out, int N, int nblocks,
    long q_off, long idx_off, long loss_off, float lscale)
{
    extern __shared__ char smem[];
    float* sxsq = reinterpret_cast<float*>(smem + OFF_XSQ);
    float* sesq = reinterpret_cast<float*>(smem + OFF_ESQ);
    float* sred = reinterpret_cast<float*>(smem + OFF_RED);
    u32 sb = smem_to_u32(smem);
    int tid = threadIdx.x, lane = tid & 31, w = tid >> 5;
    long blockbase = (long)blockIdx.x * ROWS_CTA;

    for (int i = tid; i < KCODES; i += TPB) sesq[i] = g_esqd[i];

    // Stage full B (both splits) once: 4096 uint4 per split over 512 threads.
    {
        const uint4* s0 = reinterpret_cast<const uint4*>(g_bh);
        const uint4* s1 = reinterpret_cast<const uint4*>(g_bm);
#pragma unroll
        for (int u = tid; u < KCODES * 8; u += TPB) {
            u32 sw = SW128((u32)(u * 16));
            *reinterpret_cast<uint4*>(smem + OFF_BH + sw) = s0[u];
            *reinterpret_cast<uint4*>(smem + OFF_BM + sw) = s1[u];
        }
    }

    // Threads 0..255 stage row `tid` (2 splits, SW128) + sequential-rounded xsq.
    if (tid < ROWS_CTA) {
        long row = blockbase + tid;
        bool valid = row < N;
        const float4* xr = reinterpret_cast<const float4*>(x + (valid ? row : 0) * DIM);
        float xsq = 0.f;
#pragma unroll
        for (int c = 0; c < 8; c++) {
            float4 v0 = valid ? xr[2 * c]     : make_float4(0.f, 0.f, 0.f, 0.f);
            float4 v1 = valid ? xr[2 * c + 1] : make_float4(0.f, 0.f, 0.f, 0.f);
            xsq = __fadd_rn(xsq, __fmul_rn(v0.x, v0.x));
            xsq = __fadd_rn(xsq, __fmul_rn(v0.y, v0.y));
            xsq = __fadd_rn(xsq, __fmul_rn(v0.z, v0.z));
            xsq = __fadd_rn(xsq, __fmul_rn(v0.w, v0.w));
            xsq = __fadd_rn(xsq, __fmul_rn(v1.x, v1.x));
            xsq = __fadd_rn(xsq, __fmul_rn(v1.y, v1.y));
            xsq = __fadd_rn(xsq, __fmul_rn(v1.z, v1.z));
            xsq = __fadd_rn(xsq, __fmul_rn(v1.w, v1.w));
            float f[8] = {v0.x, v0.y, v0.z, v0.w, v1.x, v1.y, v1.z, v1.w};
            u32 ph[4], pm[4];
#pragma unroll
            for (int j = 0; j < 4; j++) {
                __nv_bfloat16 ah, am, bh, bm;
                split2(f[2 * j], ah, am);
                split2(f[2 * j + 1], bh, bm);
                ph[j] = pack2(ah, bh); pm[j] = pack2(am, bm);
            }
            u32 sw = SW128((u32)(tid * 128 + c * 16));
            *reinterpret_cast<uint4*>(smem + OFF_AH + sw) = make_uint4(ph[0], ph[1], ph[2], ph[3]);
            *reinterpret_cast<uint4*>(smem + OFF_AM + sw) = make_uint4(pm[0], pm[1], pm[2], pm[3]);
        }
        sxsq[tid] = xsq;
    }
    __syncthreads();                               // ONLY sync before the mainloop

    // ldmatrix geometry. Warp w owns m-tile rows [w*16, w*16+16).
    int r4 = lane >> 2;
    int arow = w * 16 + (lane & 7) + ((lane >> 3) & 1) * 8;
    u32 aoff  = (u32)(arow * 128 + ((lane >> 4) & 1) * 16);
    u32 amask = (aoff >> 3) & 0x70;
    int n_local = (lane & 7) + ((lane >> 4) & 1) * 8;   // B x4 covers 2 n-tiles
    u32 bbase = (u32)(n_local * 128 + ((lane >> 3) & 1) * 16);
    u32 bmask = (bbase >> 3) & 0x70;

    // Hoist A fragments for both splits, all 4 k-steps (32 regs).
    u32 af[2][4][4];
#pragma unroll
    for (int s = 0; s < 2; s++) {
        u32 Abase = sb + (s ? OFF_AM : OFF_AH);
#pragma unroll
        for (int ks = 0; ks < 4; ks++)
            LDSM_X4(af[s][ks][0], af[s][ks][1], af[s][ks][2], af[s][ks][3],
                    Abase + ((aoff + ks * 32) ^ amask));
    }

    float xsqv[2];
    xsqv[0] = sxsq[w * 16 + r4];
    xsqv[1] = sxsq[w * 16 + r4 + 8];

    float best[2]  = {3.4e38f, 3.4e38f};
    float best2[2] = {3.4e38f, 3.4e38f};
    int   bidx[2]  = {0, 0};

    const int SA[3] = {0, 0, 1};                   // passes: hh, hm, mh
    const u32 OB[3] = {OFF_BH, OFF_BM, OFF_BH};

#pragma unroll 1
    for (int ch = 0; ch < NCHUNKS; ch++) {
        float acc[8][4];
#pragma unroll
        for (int nt = 0; nt < 8; nt++)
#pragma unroll
            for (int f = 0; f < 4; f++) acc[nt][f] = 0.f;

        u32 choff = (u32)(ch * 8192);              // 64 codes * 128B
#pragma unroll
        for (int p = 0; p < 3; p++) {
            u32 Bbase = sb + OB[p];
            u32 (*A)[4] = af[SA[p]];
#pragma unroll
            for (int ks = 0; ks < 4; ks++) {
#pragma unroll
                for (int np = 0; np < 4; np++) {
                    u32 b0, b1, b2, b3;
                    LDSM_X4(b0, b1, b2, b3,
                            Bbase + ((choff + (u32)(np * 2048) + bbase + ks * 32) ^ bmask));
                    MMA_BF16(acc[np * 2],     A[ks][0], A[ks][1], A[ks][2], A[ks][3], b0, b1);
                    MMA_BF16(acc[np * 2 + 1], A[ks][0], A[ks][1], A[ks][2], A[ks][3], b2, b3);
                }
            }
        }

        // Scores: s = fl(fl(xsq+esq) - fl(2*dot)); track best + runner-up.
        int cb0 = ch * 64 + (lane & 3) * 2;
#pragma unroll
        for (int nt = 0; nt < 8; nt++) {
            int code0 = cb0 + nt * 8;
            float2 e2 = *reinterpret_cast<const float2*>(sesq + code0);
#pragma unroll
            for (int fz = 0; fz < 4; fz++) {
                int slot = fz >> 1;
                int code = code0 + (fz & 1);
                float eq = (fz & 1) ? e2.y : e2.x;
                float s = __fsub_rn(__fadd_rn(xsqv[slot], eq), __fmul_rn(2.f, acc[nt][fz]));
                if (s < best[slot]) {
                    best2[slot] = best[slot];
                    best[slot] = s; bidx[slot] = code;
                } else if (s < best2[slot]) {
                    best2[slot] = s;
                }
            }
        }
    }

    // Reduce (best, idx, second) across the 4 lanes sharing each row.
#pragma unroll
    for (int off = 1; off <= 2; off <<= 1) {
#pragma unroll
        for (int c = 0; c < 2; c++) {
            float ob1 = __shfl_xor_sync(0xffffffffu, best[c],  off);
            int   oi1 = __shfl_xor_sync(0xffffffffu, bidx[c],  off);
            float ob2 = __shfl_xor_sync(0xffffffffu, best2[c], off);
            if (ob1 < best[c]) {
                best2[c] = fminf(best[c], ob2);
                best[c] = ob1; bidx[c] = oi1;
            } else if (ob1 > best[c]) {
                best2[c] = fminf(best2[c], ob1);
            } else {                               // equal firsts -> gap 0 (forces rescue)
                bidx[c] = min(bidx[c], oi1);
                best2[c] = ob1;
            }
        }
    }

    // Lanes with q<2 own one row each: q=0 -> r4, q=1 -> r4+8.
    int q = lane & 3;
    int  lrow = w * 16 + r4 + 8 * (q & 1);
    long erow = blockbase + lrow;
    bool own  = (q < 2) && (erow < N);
    int  eidx = bidx[q & 1];
    float egap = best2[q & 1] - best[q & 1];

    // Warp-cooperative near-tie rescue: full K fp32 rescan (R5-exact scheme).
    unsigned need = __ballot_sync(0xffffffffu, own && (egap < RESCUE_T));
    while (need) {
        int src = __ffs(need) - 1; need &= need - 1;
        int srow = __shfl_sync(0xffffffffu, lrow, src);
        float rxsq = sxsq[srow];
        const float4* xr = reinterpret_cast<const float4*>(x + (blockbase + srow) * DIM);
        float xv[DIM];
#pragma unroll
        for (int i = 0; i < DIM / 4; i++) {
            float4 v = xr[i];
            xv[4 * i] = v.x; xv[4 * i + 1] = v.y; xv[4 * i + 2] = v.z; xv[4 * i + 3] = v.w;
        }
        float rb = 3.4e38f; int ri = 0;
#pragma unroll 1
        for (int j = 0; j < KCODES / 32; j++) {
            int k = j * 32 + lane;                 // coalesced across lanes
            const float4* er = reinterpret_cast<const float4*>(cb + (long)k * DIM);
            float s0l = 0.f, s0h = 0.f, s1l = 0.f, s1h = 0.f;
            float s2l = 0.f, s2h = 0.f, s3l = 0.f, s3h = 0.f;
#pragma unroll
            for (int i = 0; i < DIM / 4; i++) {
                float4 e = er[i];
                if (i & 1) {
                    s2l = fmaf(xv[4 * i],     e.x, s2l);
                    s2h = fmaf(xv[4 * i + 1], e.y, s2h);
                    s3l = fmaf(xv[4 * i + 2], e.z, s3l);
                    s3h = fmaf(xv[4 * i + 3], e.w, s3h);
                } else {
                    s0l = fmaf(xv[4 * i],     e.x, s0l);
                    s0h = fmaf(xv[4 * i + 1], e.y, s0h);
                    s1l = fmaf(xv[4 * i + 2], e.z, s1l);
                    s1h = fmaf(xv[4 * i + 3], e.w, s1h);
                }
            }
            float dot = __fadd_rn(__fadd_rn(__fadd_rn(s0l, s0h), __fadd_rn(s1l, s1h)),
                                  __fadd_rn(__fadd_rn(s2l, s2h), __fadd_rn(s3l, s3h)));
            float s = __fsub_rn(__fadd_rn(rxsq, sesq[k]), __fmul_rn(2.0f, dot));
            if (s < rb) { rb = s; ri = k; }
        }
#pragma unroll
        for (int off = 16; off > 0; off >>= 1) {   // tie -> smallest index
            float ob = __shfl_xor_sync(0xffffffffu, rb, off);
            int   oi = __shfl_xor_sync(0xffffffffu, ri, off);
            if (ob < rb || (ob == rb && oi < ri)) { rb = ob; ri = oi; }
        }
        if (lane == src) eidx = ri;
    }

    // Epilogue: quantized_st = fl(x + fl(e - x)); per-row loss term.
    float lsum = 0.f;
    if (own) {
        const float4* xr = reinterpret_cast<const float4*>(x + erow * DIM);
        const float4* er = reinterpret_cast<const float4*>(cb + (long)eidx * DIM);
        bool qv = (q_off >= 0) && ((q_off & 3) == 0);
#pragma unroll
        for (int i = 0; i < DIM / 4; i++) {
            float4 xv = xr[i], ev = er[i];
            float d0 = __fsub_rn(ev.x, xv.x), d1 = __fsub_rn(ev.y, xv.y);
            float d2 = __fsub_rn(ev.z, xv.z), d3 = __fsub_rn(ev.w, xv.w);
            lsum += d0 * d0 + d1 * d1 + d2 * d2 + d3 * d3;
            if (q_off >= 0) {
                float* dst = out + q_off + erow * DIM + i * 4;
                if (qv) {
                    *reinterpret_cast<float4*>(dst) =
                        make_float4(__fadd_rn(xv.x, d0), __fadd_rn(xv.y, d1),
                                    __fadd_rn(xv.z, d2), __fadd_rn(xv.w, d3));
                } else {                           // q_off==1: 4B-aligned only
                    dst[0] = __fadd_rn(xv.x, d0); dst[1] = __fadd_rn(xv.y, d1);
                    dst[2] = __fadd_rn(xv.z, d2); dst[3] = __fadd_rn(xv.w, d3);
                }
            }
        }
        if (idx_off >= 0) out[idx_off + erow] = (float)eidx;
    }

    __shared__ int is_last;
    if (loss_off >= 0) {
        sred[tid] = lsum;
        __syncthreads();
#pragma unroll
        for (int o = TPB / 2; o > 0; o >>= 1) {
            if (tid < o) sred[tid] += sred[tid + o];
            __syncthreads();
        }
        if (tid == 0) {
            g_partials[blockIdx.x] = sred[0];
            __threadfence();
            int done = atomicAdd(&g_counter, 1);
            is_last = (done == nblocks - 1);
        }
        __syncthreads();
        if (is_last) {
            float v = 0.f;
            for (int i = tid; i < nblocks; i += TPB) v += g_partials[i];  // fixed order
            sred[tid] = v;
            __syncthreads();
#pragma unroll
            for (int o = TPB / 2; o > 0; o >>= 1) {
                if (tid < o) sred[tid] += sred[tid + o];
                __syncthreads();
            }
            if (tid == 0) { out[loss_off] = sred[0] * lscale; g_counter = 0; }
        }
    }
}

extern "C" void kernel_launch(void* const* d_in, const int* in_sizes, int n_in,
                              void* d_out, int out_size) {
    const float* a = (const float*)d_in[0];
    const float* b = (const float*)d_in[1];
    long s0 = in_sizes[0], s1 = in_sizes[1];
    const float *x, *cb; long xs, cs;
    if (s0 >= s1) { x = a; xs = s0; cb = b; cs = s1; }
    else          { x = b; xs = s1; cb = a; cs = s0; }

    int K = (int)(cs / DIM);
    int N = (int)(xs / DIM);
    long QN = (long)N * DIM;
    long osz = (long)out_size;

    // Output layout (confirmed): [loss(1), quantized_st(QN), indices(N)]
    long loss_off = -1, q_off = -1, idx_off = -1;
    if      (osz == 1 + QN + N) { loss_off = 0; q_off = 1; idx_off = 1 + QN; }
    else if (osz == QN + N)     { q_off = 0; idx_off = QN; }
    else if (osz == QN)         { q_off = 0; }
    else if (osz == N)          { idx_off = 0; }
    else if (osz == 1)          { loss_off = 0; }
    else                        { loss_off = 0; q_off = 1; idx_off = 1 + QN; }

    float* out = (float*)d_out;
    int blocks = (N + ROWS_CTA - 1) / ROWS_CTA;
    float lscale = (float)(1.25 / ((double)N * (double)DIM));

    cudaFuncSetAttribute(vq_hmma, cudaFuncAttributeMaxDynamicSharedMemorySize, SMEM_TOTAL);

    vq_prep2<<<(K + 127) / 128, 128>>>(cb, K);
    vq_hmma<<<blocks, TPB, SMEM_TOTAL>>>(x, cb, out, N, blocks,
                                         q_off, idx_off, loss_off, lscale);
}